// round 1
// baseline (speedup 1.0000x reference)
#include <cuda_runtime.h>
#include <math.h>

#define NN 50000
#define EE 400000
#define EA 450000   // EE + NN self loops
#define ED 32

// ---------------- scratch (static __device__, no allocation) ----------------
__device__ float    g_h[NN*256];     // x @ W for current layer
__device__ float    g_featA[NN*256]; // layer-1 output
__device__ float    g_featB[NN*128]; // layer-2 output
__device__ float    g_acc[NN*256];   // aggregation accumulator
__device__ float    g_ai[NN*4];
__device__ float    g_aj[NN*4];
__device__ float    g_alpha[EA*4];
__device__ unsigned g_m[NN*4];
__device__ float    g_s[NN*4];
__device__ float    g_loop[NN*ED];   // ea_sum then loop_attr (in place)
__device__ float    g_cnt[NN];

// monotone float<->uint mapping for atomicMax on floats
__device__ __forceinline__ unsigned fkey(float f){
  unsigned u = __float_as_uint(f);
  return (u & 0x80000000u) ? ~u : (u | 0x80000000u);
}
__device__ __forceinline__ float funkey(unsigned k){
  return (k & 0x80000000u) ? __uint_as_float(k & 0x7fffffffu) : __uint_as_float(~k);
}

// ---------------------------------------------------------------------------
__global__ void zero_kernel(float* __restrict__ p, int n){
  int i = blockIdx.x*blockDim.x + threadIdx.x;
  if (i < n) p[i] = 0.f;
}

// per-dst count + edge_attr sum (layer invariant)
__global__ void cnt_sum_kernel(const int* __restrict__ dst, const float* __restrict__ ea,
                               float* __restrict__ cnt, float* __restrict__ easum){
  int idx = blockIdx.x*blockDim.x + threadIdx.x;
  if (idx >= EE*ED) return;
  int e = idx >> 5, d = idx & 31;
  int dn = dst[e];
  atomicAdd(&easum[dn*ED + d], ea[idx]);
  if (d == 0) atomicAdd(&cnt[dn], 1.0f);
}

__global__ void loop_fin_kernel(float* __restrict__ lp, const float* __restrict__ cnt){
  int idx = blockIdx.x*blockDim.x + threadIdx.x;
  if (idx >= NN*ED) return;
  float c = cnt[idx >> 5];
  lp[idx] = (c > 0.f) ? lp[idx]/c : 0.f;
}

// per-node attention scalars  a_i = <h[n,h,:],att_i[h]>,  a_j likewise.
// Also (re)initializes the softmax max/sum accumulators for this layer.
__global__ void aij_kernel(const float* __restrict__ h, const float* __restrict__ att,
                           float* __restrict__ ai, float* __restrict__ aj,
                           unsigned* __restrict__ m, float* __restrict__ s,
                           int H, int C){
  int idx = blockIdx.x*blockDim.x + threadIdx.x;
  if (idx >= NN*H) return;
  int n = idx / H, hh = idx - n*H;
  int stride = 2*C + ED;
  const float* atti = att + hh*stride;
  const float* attj = atti + C;
  const float* hv = h + ((size_t)n*H + hh)*C;
  float si = 0.f, sj = 0.f;
  for (int c = 0; c < C; c++){ float v = hv[c]; si += v*atti[c]; sj += v*attj[c]; }
  ai[idx] = si; aj[idx] = sj;
  m[idx] = 0u;   // key-space minimum (< key of any finite float)
  s[idx] = 0.f;
}

// per augmented edge: edge MLP -> gate -> att_e dot, add a_i+a_j, leaky_relu,
// store raw logit, atomicMax per (dst, head)
template<int H>
__global__ void edge_alpha_kernel(const int* __restrict__ src, const int* __restrict__ dst,
    const float* __restrict__ ea, const float* __restrict__ loopattr,
    const float* __restrict__ ew1, const float* __restrict__ eb1,
    const float* __restrict__ ew2, const float* __restrict__ eb2,
    const float* __restrict__ att, int C,
    const float* __restrict__ ai, const float* __restrict__ aj,
    float* __restrict__ alpha, unsigned* __restrict__ m){
  __shared__ float s_ew1[512], s_ew2[512], s_eb1[16], s_eb2[32], s_att[H*32];
  int t = threadIdx.x;
  for (int i = t; i < 512; i += 256){ s_ew1[i] = ew1[i]; s_ew2[i] = ew2[i]; }
  if (t < 16) s_eb1[t] = eb1[t];
  else if (t < 48) s_eb2[t-16] = eb2[t-16];
  for (int i = t; i < H*32; i += 256){
    int hh = i >> 5, d = i & 31;
    s_att[i] = att[hh*(2*C+ED) + 2*C + d];
  }
  __syncthreads();

  int e = blockIdx.x*blockDim.x + t;
  if (e >= EA) return;
  int sN, dN; const float* eav;
  if (e < EE){ sN = src[e]; dN = dst[e]; eav = ea + (size_t)e*ED; }
  else       { sN = dN = e - EE;         eav = loopattr + (size_t)(e-EE)*ED; }

  float eaL[32];
  #pragma unroll
  for (int d = 0; d < 32; d += 4){
    float4 v = *reinterpret_cast<const float4*>(eav + d);
    eaL[d] = v.x; eaL[d+1] = v.y; eaL[d+2] = v.z; eaL[d+3] = v.w;
  }
  float hid[16];
  #pragma unroll
  for (int j = 0; j < 16; j++) hid[j] = s_eb1[j];
  #pragma unroll
  for (int d = 0; d < 32; d++){
    float a = eaL[d];
    #pragma unroll
    for (int j = 0; j < 16; j++) hid[j] += a * s_ew1[d*16 + j];
  }
  #pragma unroll
  for (int j = 0; j < 16; j++) hid[j] = fmaxf(hid[j], 0.f);

  float acc[H];
  #pragma unroll
  for (int h = 0; h < H; h++) acc[h] = 0.f;
  #pragma unroll
  for (int d = 0; d < 32; d++){
    float o = s_eb2[d];
    #pragma unroll
    for (int j = 0; j < 16; j++) o += hid[j] * s_ew2[j*32 + d];
    float cw = 1.f / (1.f + expf(-o));
    float ew = eaL[d] * cw;
    #pragma unroll
    for (int h = 0; h < H; h++) acc[h] += ew * s_att[h*32 + d];
  }
  #pragma unroll
  for (int h = 0; h < H; h++){
    float tt  = ai[dN*H + h] + aj[sN*H + h] + acc[h];
    float raw = tt > 0.f ? tt : 0.2f*tt;
    alpha[(size_t)e*H + h] = raw;
    atomicMax(&m[dN*H + h], fkey(raw));
  }
}

// exp(raw - max) and per-(dst,head) sum
__global__ void edge_exp_kernel(const int* __restrict__ dst, float* __restrict__ alpha,
                                const unsigned* __restrict__ m, float* __restrict__ s, int H){
  int idx = blockIdx.x*blockDim.x + threadIdx.x;
  if (idx >= EA*H) return;
  int e = idx / H, h = idx - e*H;
  int dN = (e < EE) ? dst[e] : e - EE;
  float mv = funkey(m[dN*H + h]);
  float v = expf(alpha[idx] - mv);
  alpha[idx] = v;
  atomicAdd(&s[dN*H + h], v);
}

// out[dst] += h[src] * (e/(s+1e-16)), one warp per edge, float4 atomics
template<int H, int C>
__global__ void aggregate_kernel(const int* __restrict__ src, const int* __restrict__ dst,
    const float* __restrict__ h, const float* __restrict__ alpha,
    const float* __restrict__ s, float* __restrict__ out){
  const int HC = H*C;
  int gw   = (blockIdx.x*blockDim.x + threadIdx.x) >> 5;
  int lane = threadIdx.x & 31;
  int nw   = (gridDim.x*blockDim.x) >> 5;
  for (int e = gw; e < EA; e += nw){
    int sN, dN;
    if (e < EE){ sN = src[e]; dN = dst[e]; } else { sN = dN = e - EE; }
    const float4* hp = reinterpret_cast<const float4*>(h + (size_t)sN*HC);
    float* op = out + (size_t)dN*HC;
    #pragma unroll
    for (int j = lane; j < HC/4; j += 32){
      int head = (j*4)/C;
      float w = alpha[(size_t)e*H + head] / (s[dN*H + head] + 1e-16f);
      float4 v = hp[j];
      v.x *= w; v.y *= w; v.z *= w; v.w *= w;
#if __CUDA_ARCH__ >= 900
      atomicAdd(reinterpret_cast<float4*>(op + j*4), v);
#else
      atomicAdd(op + j*4 + 0, v.x); atomicAdd(op + j*4 + 1, v.y);
      atomicAdd(op + j*4 + 2, v.z); atomicAdd(op + j*4 + 3, v.w);
#endif
    }
  }
}

// bias + BN(eval) + ELU
__global__ void post_bn_kernel(const float* __restrict__ acc, const float* __restrict__ bias,
   const float* __restrict__ gamma, const float* __restrict__ beta,
   const float* __restrict__ mean, const float* __restrict__ var,
   float* __restrict__ outp, int HC){
  int idx = blockIdx.x*blockDim.x + threadIdx.x;
  if (idx >= NN*HC) return;
  int c = idx % HC;
  float v = acc[idx] + bias[c];
  v = (v - mean[c]) * rsqrtf(var[c] + 1e-5f) * gamma[c] + beta[c];
  outp[idx] = v > 0.f ? v : expf(v) - 1.f;
}

__global__ void post_final_kernel(const float* __restrict__ acc, const float* __restrict__ bias,
                                  float* __restrict__ outp){
  int idx = blockIdx.x*blockDim.x + threadIdx.x;
  if (idx >= NN*64) return;
  outp[idx] = acc[idx] + bias[idx & 63];
}

// C[M,N] = A[M,K] @ B[K,N], fp32, 64x64 tile / 16 K-slice / 4x4 per thread
__global__ void gemm_kernel(const float* __restrict__ A, const float* __restrict__ B,
                            float* __restrict__ C, int M, int K, int N){
  __shared__ float As[16][64];
  __shared__ float Bs[16][64];
  int tid = threadIdx.x;
  int tx = tid & 15, ty = tid >> 4;
  int rowBase = blockIdx.y*64, colBase = blockIdx.x*64;
  float acc[4][4];
  #pragma unroll
  for (int i = 0; i < 4; i++)
    #pragma unroll
    for (int j = 0; j < 4; j++) acc[i][j] = 0.f;

  for (int k0 = 0; k0 < K; k0 += 16){
    #pragma unroll
    for (int i = 0; i < 4; i++){
      int t  = tid + i*256;
      int mm = t >> 4, kk = t & 15;
      int gr = rowBase + mm;
      As[kk][mm] = (gr < M) ? A[(size_t)gr*K + k0 + kk] : 0.f;
    }
    #pragma unroll
    for (int i = 0; i < 4; i++){
      int t  = tid + i*256;
      int kk = t >> 6, nn = t & 63;
      Bs[kk][nn] = B[(size_t)(k0 + kk)*N + colBase + nn];
    }
    __syncthreads();
    #pragma unroll
    for (int kk = 0; kk < 16; kk++){
      float4 a = *reinterpret_cast<const float4*>(&As[kk][ty*4]);
      float4 b = *reinterpret_cast<const float4*>(&Bs[kk][tx*4]);
      float av[4] = {a.x,a.y,a.z,a.w};
      float bv[4] = {b.x,b.y,b.z,b.w};
      #pragma unroll
      for (int i = 0; i < 4; i++)
        #pragma unroll
        for (int j = 0; j < 4; j++) acc[i][j] += av[i]*bv[j];
    }
    __syncthreads();
  }
  #pragma unroll
  for (int i = 0; i < 4; i++){
    int row = rowBase + ty*4 + i;
    if (row < M){
      #pragma unroll
      for (int j = 0; j < 4; j++)
        C[(size_t)row*N + colBase + tx*4 + j] = acc[i][j];
    }
  }
}

// ---------------------------------------------------------------------------
static inline int cdiv(int a, int b){ return (a + b - 1)/b; }

extern "C" void kernel_launch(void* const* d_in, const int* in_sizes, int n_in,
                              void* d_out, int out_size){
  const float* x   = (const float*)d_in[0];
  const int*   ei  = (const int*)  d_in[1];
  const float* ea  = (const float*)d_in[2];
  const float *g1W   =(const float*)d_in[3],  *g1e1=(const float*)d_in[4],  *g1b1=(const float*)d_in[5],
              *g1e2  =(const float*)d_in[6],  *g1b2=(const float*)d_in[7],  *g1att=(const float*)d_in[8],
              *g1bias=(const float*)d_in[9];
  const float *g2W   =(const float*)d_in[10], *g2e1=(const float*)d_in[11], *g2b1=(const float*)d_in[12],
              *g2e2  =(const float*)d_in[13], *g2b2=(const float*)d_in[14], *g2att=(const float*)d_in[15],
              *g2bias=(const float*)d_in[16];
  const float *g3W   =(const float*)d_in[17], *g3e1=(const float*)d_in[18], *g3b1=(const float*)d_in[19],
              *g3e2  =(const float*)d_in[20], *g3b2=(const float*)d_in[21], *g3att=(const float*)d_in[22],
              *g3bias=(const float*)d_in[23];
  const float *bn1g=(const float*)d_in[24], *bn1b=(const float*)d_in[25],
              *bn1m=(const float*)d_in[26], *bn1v=(const float*)d_in[27];
  const float *bn2g=(const float*)d_in[28], *bn2b=(const float*)d_in[29],
              *bn2m=(const float*)d_in[30], *bn2v=(const float*)d_in[31];
  const int* srcp = ei;
  const int* dstp = ei + EE;
  float* outp = (float*)d_out;

  float *ph, *pfA, *pfB, *pacc, *pai, *paj, *palpha, *ps, *ploop, *pcnt;
  unsigned* pm;
  cudaGetSymbolAddress((void**)&ph,     g_h);
  cudaGetSymbolAddress((void**)&pfA,    g_featA);
  cudaGetSymbolAddress((void**)&pfB,    g_featB);
  cudaGetSymbolAddress((void**)&pacc,   g_acc);
  cudaGetSymbolAddress((void**)&pai,    g_ai);
  cudaGetSymbolAddress((void**)&paj,    g_aj);
  cudaGetSymbolAddress((void**)&palpha, g_alpha);
  cudaGetSymbolAddress((void**)&pm,     g_m);
  cudaGetSymbolAddress((void**)&ps,     g_s);
  cudaGetSymbolAddress((void**)&ploop,  g_loop);
  cudaGetSymbolAddress((void**)&pcnt,   g_cnt);

  const int TB = 256;

  // -------- layer-invariant self-loop attributes --------
  zero_kernel<<<cdiv(NN*ED,TB),TB>>>(ploop, NN*ED);
  zero_kernel<<<cdiv(NN,TB),TB>>>(pcnt, NN);
  cnt_sum_kernel<<<cdiv(EE*ED,TB),TB>>>(dstp, ea, pcnt, ploop);
  loop_fin_kernel<<<cdiv(NN*ED,TB),TB>>>(ploop, pcnt);

  // -------- layer 1: 128 -> 4x64 (concat 256), BN1 + ELU --------
  {
    const int K=128, H=4, C=64, HC=256;
    dim3 g(HC/64, cdiv(NN,64));
    gemm_kernel<<<g,256>>>(x, g1W, ph, NN, K, HC);
    aij_kernel<<<cdiv(NN*H,TB),TB>>>(ph, g1att, pai, paj, pm, ps, H, C);
    edge_alpha_kernel<4><<<cdiv(EA,TB),TB>>>(srcp,dstp,ea,ploop,g1e1,g1b1,g1e2,g1b2,g1att,C,pai,paj,palpha,pm);
    edge_exp_kernel<<<cdiv(EA*H,TB),TB>>>(dstp,palpha,pm,ps,H);
    zero_kernel<<<cdiv(NN*HC,TB),TB>>>(pacc, NN*HC);
    aggregate_kernel<4,64><<<cdiv(EA,8),TB>>>(srcp,dstp,ph,palpha,ps,pacc);
    post_bn_kernel<<<cdiv(NN*HC,TB),TB>>>(pacc,g1bias,bn1g,bn1b,bn1m,bn1v,pfA,HC);
  }

  // -------- layer 2: 256 -> 4x32 (concat 128), BN2 + ELU --------
  {
    const int K=256, H=4, C=32, HC=128;
    dim3 g(HC/64, cdiv(NN,64));
    gemm_kernel<<<g,256>>>(pfA, g2W, ph, NN, K, HC);
    aij_kernel<<<cdiv(NN*H,TB),TB>>>(ph, g2att, pai, paj, pm, ps, H, C);
    edge_alpha_kernel<4><<<cdiv(EA,TB),TB>>>(srcp,dstp,ea,ploop,g2e1,g2b1,g2e2,g2b2,g2att,C,pai,paj,palpha,pm);
    edge_exp_kernel<<<cdiv(EA*H,TB),TB>>>(dstp,palpha,pm,ps,H);
    zero_kernel<<<cdiv(NN*HC,TB),TB>>>(pacc, NN*HC);
    aggregate_kernel<4,32><<<cdiv(EA,8),TB>>>(srcp,dstp,ph,palpha,ps,pacc);
    post_bn_kernel<<<cdiv(NN*HC,TB),TB>>>(pacc,g2bias,bn2g,bn2b,bn2m,bn2v,pfB,HC);
  }

  // -------- layer 3: 128 -> 1x64 (mean over 1 head = identity) --------
  {
    const int K=128, H=1, C=64, HC=64;
    dim3 g(HC/64, cdiv(NN,64));
    gemm_kernel<<<g,256>>>(pfB, g3W, ph, NN, K, HC);
    aij_kernel<<<cdiv(NN*H,TB),TB>>>(ph, g3att, pai, paj, pm, ps, H, C);
    edge_alpha_kernel<1><<<cdiv(EA,TB),TB>>>(srcp,dstp,ea,ploop,g3e1,g3b1,g3e2,g3b2,g3att,C,pai,paj,palpha,pm);
    edge_exp_kernel<<<cdiv(EA*H,TB),TB>>>(dstp,palpha,pm,ps,H);
    zero_kernel<<<cdiv(NN*HC,TB),TB>>>(pacc, NN*HC);
    aggregate_kernel<1,64><<<cdiv(EA,8),TB>>>(srcp,dstp,ph,palpha,ps,pacc);
    post_final_kernel<<<cdiv(NN*64,TB),TB>>>(pacc, g3bias, outp);
  }
}

// round 2
// speedup vs baseline: 1.1850x; 1.1850x over previous
#include <cuda_runtime.h>
#include <math.h>

#define NN 50000
#define EE 400000
#define EA 450000   // EE + NN self loops
#define ED 32

// ---------------- scratch (static __device__, no allocation) ----------------
__device__ float    g_h[NN*256];     // x @ W for current layer
__device__ float    g_featA[NN*256]; // layer-1 output
__device__ float    g_featB[NN*128]; // layer-2 output
__device__ float    g_acc[NN*256];   // aggregation accumulator (unnormalized)
__device__ float    g_ai[NN*4];
__device__ float    g_aj[NN*4];
__device__ float    g_alpha[EA*4];   // raw logits
__device__ unsigned g_m[NN*4];
__device__ float    g_s[NN*4];
__device__ float    g_loop[NN*ED];   // ea_sum then loop_attr (in place)
__device__ float    g_cnt[NN];

// monotone float<->uint mapping for atomicMax on floats
__device__ __forceinline__ unsigned fkey(float f){
  unsigned u = __float_as_uint(f);
  return (u & 0x80000000u) ? ~u : (u | 0x80000000u);
}
__device__ __forceinline__ float funkey(unsigned k){
  return (k & 0x80000000u) ? __uint_as_float(k & 0x7fffffffu) : __uint_as_float(~k);
}

// ---------------------------------------------------------------------------
__global__ void zero_kernel(float* __restrict__ p, int n){
  int i = blockIdx.x*blockDim.x + threadIdx.x;
  if (i < n) p[i] = 0.f;
}

// per-dst count + edge_attr sum (layer invariant), float4 atomics
__global__ void cnt_sum_kernel(const int* __restrict__ dst, const float* __restrict__ ea,
                               float* __restrict__ cnt, float* __restrict__ easum){
  int idx = blockIdx.x*blockDim.x + threadIdx.x;
  if (idx >= EE*8) return;
  int e = idx >> 3, q = idx & 7;
  int dn = dst[e];
  float4 v = *reinterpret_cast<const float4*>(ea + (size_t)e*ED + q*4);
#if __CUDA_ARCH__ >= 900
  atomicAdd(reinterpret_cast<float4*>(easum + (size_t)dn*ED + q*4), v);
#else
  atomicAdd(easum + dn*ED + q*4 + 0, v.x); atomicAdd(easum + dn*ED + q*4 + 1, v.y);
  atomicAdd(easum + dn*ED + q*4 + 2, v.z); atomicAdd(easum + dn*ED + q*4 + 3, v.w);
#endif
  if (q == 0) atomicAdd(&cnt[dn], 1.0f);
}

__global__ void loop_fin_kernel(float* __restrict__ lp, const float* __restrict__ cnt){
  int idx = blockIdx.x*blockDim.x + threadIdx.x;
  if (idx >= NN*8) return;
  float c = cnt[idx >> 3];
  float4* p = reinterpret_cast<float4*>(lp) + idx;
  float4 v = *p;
  float inv = (c > 0.f) ? 1.f/c : 0.f;
  v.x *= inv; v.y *= inv; v.z *= inv; v.w *= inv;
  *p = v;
}

// per-node attention scalars  a_i = <h[n,h,:],att_i[h]>,  a_j likewise.
// Also (re)initializes the softmax max/sum accumulators for this layer.
__global__ void aij_kernel(const float* __restrict__ h, const float* __restrict__ att,
                           float* __restrict__ ai, float* __restrict__ aj,
                           unsigned* __restrict__ m, float* __restrict__ s,
                           int H, int C){
  int idx = blockIdx.x*blockDim.x + threadIdx.x;
  if (idx >= NN*H) return;
  int n = idx / H, hh = idx - n*H;
  int stride = 2*C + ED;
  const float4* atti = reinterpret_cast<const float4*>(att + hh*stride);
  const float4* attj = reinterpret_cast<const float4*>(att + hh*stride + C);
  const float4* hv   = reinterpret_cast<const float4*>(h + ((size_t)n*H + hh)*C);
  float si = 0.f, sj = 0.f;
  for (int c = 0; c < C/4; c++){
    float4 v = hv[c], a = atti[c], b = attj[c];
    si += v.x*a.x + v.y*a.y + v.z*a.z + v.w*a.w;
    sj += v.x*b.x + v.y*b.y + v.z*b.z + v.w*b.w;
  }
  ai[idx] = si; aj[idx] = sj;
  m[idx] = 0u;   // key-space minimum (< key of any finite float)
  s[idx] = 0.f;
}

// per augmented edge: edge MLP -> gate -> att_e dot, add a_i+a_j, leaky_relu,
// store raw logit, atomicMax per (dst, head)
template<int H>
__global__ void edge_alpha_kernel(const int* __restrict__ src, const int* __restrict__ dst,
    const float* __restrict__ ea, const float* __restrict__ loopattr,
    const float* __restrict__ ew1, const float* __restrict__ eb1,
    const float* __restrict__ ew2, const float* __restrict__ eb2,
    const float* __restrict__ att, int C,
    const float* __restrict__ ai, const float* __restrict__ aj,
    float* __restrict__ alpha, unsigned* __restrict__ m){
  __shared__ float s_ew1[512], s_ew2[512], s_eb1[16], s_eb2[32], s_att[H*32];
  int t = threadIdx.x;
  for (int i = t; i < 512; i += 256){ s_ew1[i] = ew1[i]; s_ew2[i] = ew2[i]; }
  if (t < 16) s_eb1[t] = eb1[t];
  else if (t < 48) s_eb2[t-16] = eb2[t-16];
  for (int i = t; i < H*32; i += 256){
    int hh = i >> 5, d = i & 31;
    s_att[i] = att[hh*(2*C+ED) + 2*C + d];
  }
  __syncthreads();

  int e = blockIdx.x*blockDim.x + t;
  if (e >= EA) return;
  int sN, dN; const float* eav;
  if (e < EE){ sN = src[e]; dN = dst[e]; eav = ea + (size_t)e*ED; }
  else       { sN = dN = e - EE;         eav = loopattr + (size_t)(e-EE)*ED; }

  float eaL[32];
  #pragma unroll
  for (int d = 0; d < 32; d += 4){
    float4 v = *reinterpret_cast<const float4*>(eav + d);
    eaL[d] = v.x; eaL[d+1] = v.y; eaL[d+2] = v.z; eaL[d+3] = v.w;
  }
  float hid[16];
  #pragma unroll
  for (int j = 0; j < 16; j++) hid[j] = s_eb1[j];
  #pragma unroll
  for (int d = 0; d < 32; d++){
    float a = eaL[d];
    #pragma unroll
    for (int j = 0; j < 16; j++) hid[j] += a * s_ew1[d*16 + j];
  }
  #pragma unroll
  for (int j = 0; j < 16; j++) hid[j] = fmaxf(hid[j], 0.f);

  float acc[H];
  #pragma unroll
  for (int h = 0; h < H; h++) acc[h] = 0.f;
  #pragma unroll
  for (int d = 0; d < 32; d++){
    float o = s_eb2[d];
    #pragma unroll
    for (int j = 0; j < 16; j++) o += hid[j] * s_ew2[j*32 + d];
    float cw = 1.f / (1.f + expf(-o));
    float ew = eaL[d] * cw;
    #pragma unroll
    for (int h = 0; h < H; h++) acc[h] += ew * s_att[h*32 + d];
  }
  #pragma unroll
  for (int h = 0; h < H; h++){
    float tt  = ai[dN*H + h] + aj[sN*H + h] + acc[h];
    float raw = tt > 0.f ? tt : 0.2f*tt;
    alpha[(size_t)e*H + h] = raw;
    atomicMax(&m[dN*H + h], fkey(raw));
  }
}

// fused exp + sum + unnormalized aggregation:
//   e_eh = exp(raw - m[d,h]);  s[d,h] += e_eh;  acc[d] += e_eh * h[src]
// one warp per edge, float4 atomics
template<int H, int C>
__global__ void aggregate_kernel(const int* __restrict__ src, const int* __restrict__ dst,
    const float* __restrict__ h, const float* __restrict__ alpha,
    const unsigned* __restrict__ m, float* __restrict__ s, float* __restrict__ out){
  const int HC = H*C;
  int gw   = (blockIdx.x*blockDim.x + threadIdx.x) >> 5;
  int lane = threadIdx.x & 31;
  int nw   = (gridDim.x*blockDim.x) >> 5;
  for (int e = gw; e < EA; e += nw){
    int sN, dN;
    if (e < EE){ sN = src[e]; dN = dst[e]; } else { sN = dN = e - EE; }
    float ev = 0.f;
    if (lane < H){
      float raw = alpha[(size_t)e*H + lane];
      float mv  = funkey(m[dN*H + lane]);
      ev = expf(raw - mv);
      atomicAdd(&s[dN*H + lane], ev);
    }
    const float4* hp = reinterpret_cast<const float4*>(h + (size_t)sN*HC);
    float* op = out + (size_t)dN*HC;
    #pragma unroll
    for (int j = lane; j < HC/4; j += 32){
      int head = (j*4)/C;
      float w = __shfl_sync(0xffffffffu, ev, head);
      float4 v = hp[j];
      v.x *= w; v.y *= w; v.z *= w; v.w *= w;
#if __CUDA_ARCH__ >= 900
      atomicAdd(reinterpret_cast<float4*>(op + j*4), v);
#else
      atomicAdd(op + j*4 + 0, v.x); atomicAdd(op + j*4 + 1, v.y);
      atomicAdd(op + j*4 + 2, v.z); atomicAdd(op + j*4 + 3, v.w);
#endif
    }
  }
}

// normalize (divide by softmax sum) + bias + BN(eval) + ELU
__global__ void post_bn_kernel(const float* __restrict__ acc, const float* __restrict__ s,
   const float* __restrict__ bias,
   const float* __restrict__ gamma, const float* __restrict__ beta,
   const float* __restrict__ mean, const float* __restrict__ var,
   float* __restrict__ outp, int H, int C){
  int HC = H*C;
  int idx = blockIdx.x*blockDim.x + threadIdx.x;
  if (idx >= NN*HC) return;
  int c = idx % HC;
  int n = idx / HC;
  float sv = s[n*H + c/C] + 1e-16f;
  float v = acc[idx]/sv + bias[c];
  v = (v - mean[c]) * rsqrtf(var[c] + 1e-5f) * gamma[c] + beta[c];
  outp[idx] = v > 0.f ? v : expf(v) - 1.f;
}

__global__ void post_final_kernel(const float* __restrict__ acc, const float* __restrict__ s,
                                  const float* __restrict__ bias, float* __restrict__ outp){
  int idx = blockIdx.x*blockDim.x + threadIdx.x;
  if (idx >= NN*64) return;
  int n = idx >> 6;
  float sv = s[n] + 1e-16f;
  outp[idx] = acc[idx]/sv + bias[idx & 63];
}

// C[M,N] = A[M,K] @ B[K,N], fp32. 128x64 tile, BK=16, 8x4 microtile, 256 thr.
__global__ void gemm_kernel(const float* __restrict__ A, const float* __restrict__ B,
                            float* __restrict__ C, int M, int K, int N){
  __shared__ float As[16][136];   // padded: transpose-store banks {0,8,16,24}
  __shared__ float Bs[16][64];
  int tid = threadIdx.x;
  int tx = tid & 15;        // 16 cols of 4
  int ty = tid >> 4;        // 16 rows of 8
  int rowBase = blockIdx.y*128, colBase = blockIdx.x*64;

  float acc[8][4];
  #pragma unroll
  for (int i = 0; i < 8; i++)
    #pragma unroll
    for (int j = 0; j < 4; j++) acc[i][j] = 0.f;

  for (int k0 = 0; k0 < K; k0 += 16){
    // load A tile 128x16 (512 float4), transpose into As
    #pragma unroll
    for (int i = 0; i < 2; i++){
      int lin = tid + i*256;       // float4 index
      int row = lin >> 2;          // 0..127
      int kq  = lin & 3;           // col group of 4
      int gr  = rowBase + row;
      float4 v = make_float4(0.f,0.f,0.f,0.f);
      if (gr < M) v = *reinterpret_cast<const float4*>(A + (size_t)gr*K + k0 + kq*4);
      As[kq*4+0][row] = v.x; As[kq*4+1][row] = v.y;
      As[kq*4+2][row] = v.z; As[kq*4+3][row] = v.w;
    }
    // load B tile 16x64 (256 float4), direct
    {
      int kk = tid >> 4;           // 0..15
      int nq = tid & 15;           // 0..15
      *reinterpret_cast<float4*>(&Bs[kk][nq*4]) =
        *reinterpret_cast<const float4*>(B + (size_t)(k0+kk)*N + colBase + nq*4);
    }
    __syncthreads();
    #pragma unroll
    for (int kk = 0; kk < 16; kk++){
      float4 a0 = *reinterpret_cast<const float4*>(&As[kk][ty*8]);
      float4 a1 = *reinterpret_cast<const float4*>(&As[kk][ty*8+4]);
      float4 b  = *reinterpret_cast<const float4*>(&Bs[kk][tx*4]);
      float av[8] = {a0.x,a0.y,a0.z,a0.w,a1.x,a1.y,a1.z,a1.w};
      float bv[4] = {b.x,b.y,b.z,b.w};
      #pragma unroll
      for (int i = 0; i < 8; i++)
        #pragma unroll
        for (int j = 0; j < 4; j++) acc[i][j] += av[i]*bv[j];
    }
    __syncthreads();
  }
  #pragma unroll
  for (int i = 0; i < 8; i++){
    int row = rowBase + ty*8 + i;
    if (row < M){
      float4 v = make_float4(acc[i][0],acc[i][1],acc[i][2],acc[i][3]);
      *reinterpret_cast<float4*>(C + (size_t)row*N + colBase + tx*4) = v;
    }
  }
}

// ---------------------------------------------------------------------------
static inline int cdiv(int a, int b){ return (a + b - 1)/b; }

extern "C" void kernel_launch(void* const* d_in, const int* in_sizes, int n_in,
                              void* d_out, int out_size){
  const float* x   = (const float*)d_in[0];
  const int*   ei  = (const int*)  d_in[1];
  const float* ea  = (const float*)d_in[2];
  const float *g1W   =(const float*)d_in[3],  *g1e1=(const float*)d_in[4],  *g1b1=(const float*)d_in[5],
              *g1e2  =(const float*)d_in[6],  *g1b2=(const float*)d_in[7],  *g1att=(const float*)d_in[8],
              *g1bias=(const float*)d_in[9];
  const float *g2W   =(const float*)d_in[10], *g2e1=(const float*)d_in[11], *g2b1=(const float*)d_in[12],
              *g2e2  =(const float*)d_in[13], *g2b2=(const float*)d_in[14], *g2att=(const float*)d_in[15],
              *g2bias=(const float*)d_in[16];
  const float *g3W   =(const float*)d_in[17], *g3e1=(const float*)d_in[18], *g3b1=(const float*)d_in[19],
              *g3e2  =(const float*)d_in[20], *g3b2=(const float*)d_in[21], *g3att=(const float*)d_in[22],
              *g3bias=(const float*)d_in[23];
  const float *bn1g=(const float*)d_in[24], *bn1b=(const float*)d_in[25],
              *bn1m=(const float*)d_in[26], *bn1v=(const float*)d_in[27];
  const float *bn2g=(const float*)d_in[28], *bn2b=(const float*)d_in[29],
              *bn2m=(const float*)d_in[30], *bn2v=(const float*)d_in[31];
  const int* srcp = ei;
  const int* dstp = ei + EE;
  float* outp = (float*)d_out;

  float *ph, *pfA, *pfB, *pacc, *pai, *paj, *palpha, *ps, *ploop, *pcnt;
  unsigned* pm;
  cudaGetSymbolAddress((void**)&ph,     g_h);
  cudaGetSymbolAddress((void**)&pfA,    g_featA);
  cudaGetSymbolAddress((void**)&pfB,    g_featB);
  cudaGetSymbolAddress((void**)&pacc,   g_acc);
  cudaGetSymbolAddress((void**)&pai,    g_ai);
  cudaGetSymbolAddress((void**)&paj,    g_aj);
  cudaGetSymbolAddress((void**)&palpha, g_alpha);
  cudaGetSymbolAddress((void**)&pm,     g_m);
  cudaGetSymbolAddress((void**)&ps,     g_s);
  cudaGetSymbolAddress((void**)&ploop,  g_loop);
  cudaGetSymbolAddress((void**)&pcnt,   g_cnt);

  const int TB = 256;

  // -------- layer-invariant self-loop attributes --------
  zero_kernel<<<cdiv(NN*ED,TB),TB>>>(ploop, NN*ED);
  zero_kernel<<<cdiv(NN,TB),TB>>>(pcnt, NN);
  cnt_sum_kernel<<<cdiv(EE*8,TB),TB>>>(dstp, ea, pcnt, ploop);
  loop_fin_kernel<<<cdiv(NN*8,TB),TB>>>(ploop, pcnt);

  // -------- layer 1: 128 -> 4x64 (concat 256), BN1 + ELU --------
  {
    const int K=128, H=4, C=64, HC=256;
    dim3 g(HC/64, cdiv(NN,128));
    gemm_kernel<<<g,256>>>(x, g1W, ph, NN, K, HC);
    aij_kernel<<<cdiv(NN*H,TB),TB>>>(ph, g1att, pai, paj, pm, ps, H, C);
    edge_alpha_kernel<4><<<cdiv(EA,TB),TB>>>(srcp,dstp,ea,ploop,g1e1,g1b1,g1e2,g1b2,g1att,C,pai,paj,palpha,pm);
    zero_kernel<<<cdiv(NN*HC,TB),TB>>>(pacc, NN*HC);
    aggregate_kernel<4,64><<<cdiv(EA,8),TB>>>(srcp,dstp,ph,palpha,pm,ps,pacc);
    post_bn_kernel<<<cdiv(NN*HC,TB),TB>>>(pacc,ps,g1bias,bn1g,bn1b,bn1m,bn1v,pfA,H,C);
  }

  // -------- layer 2: 256 -> 4x32 (concat 128), BN2 + ELU --------
  {
    const int K=256, H=4, C=32, HC=128;
    dim3 g(HC/64, cdiv(NN,128));
    gemm_kernel<<<g,256>>>(pfA, g2W, ph, NN, K, HC);
    aij_kernel<<<cdiv(NN*H,TB),TB>>>(ph, g2att, pai, paj, pm, ps, H, C);
    edge_alpha_kernel<4><<<cdiv(EA,TB),TB>>>(srcp,dstp,ea,ploop,g2e1,g2b1,g2e2,g2b2,g2att,C,pai,paj,palpha,pm);
    zero_kernel<<<cdiv(NN*HC,TB),TB>>>(pacc, NN*HC);
    aggregate_kernel<4,32><<<cdiv(EA,8),TB>>>(srcp,dstp,ph,palpha,pm,ps,pacc);
    post_bn_kernel<<<cdiv(NN*HC,TB),TB>>>(pacc,ps,g2bias,bn2g,bn2b,bn2m,bn2v,pfB,H,C);
  }

  // -------- layer 3: 128 -> 1x64 (mean over 1 head = identity) --------
  {
    const int K=128, H=1, C=64, HC=64;
    dim3 g(HC/64, cdiv(NN,128));
    gemm_kernel<<<g,256>>>(pfB, g3W, ph, NN, K, HC);
    aij_kernel<<<cdiv(NN*H,TB),TB>>>(ph, g3att, pai, paj, pm, ps, H, C);
    edge_alpha_kernel<1><<<cdiv(EA,TB),TB>>>(srcp,dstp,ea,ploop,g3e1,g3b1,g3e2,g3b2,g3att,C,pai,paj,palpha,pm);
    zero_kernel<<<cdiv(NN*HC,TB),TB>>>(pacc, NN*HC);
    aggregate_kernel<1,64><<<cdiv(EA,8),TB>>>(srcp,dstp,ph,palpha,pm,ps,pacc);
    post_final_kernel<<<cdiv(NN*64,TB),TB>>>(pacc, ps, g3bias, outp);
  }
}

// round 4
// speedup vs baseline: 1.4849x; 1.2531x over previous
#include <cuda_runtime.h>
#include <math.h>

#define NN 50000
#define EE 400000
#define EA 450000   // EE + NN self loops
#define ED 32

// ---------------- scratch (static __device__, no allocation) ----------------
__device__ float g_h[NN*256];      // x @ W for current layer
__device__ float g_featA[NN*256];  // layer-1 output
__device__ float g_featB[NN*128];  // layer-2 output
__device__ float g_ai[NN*4];
__device__ float g_aj[NN*4];
__device__ float g_alpha[EA*4];    // raw logits
__device__ float g_loop[NN*ED];    // loop_attr
__device__ int   g_deg[NN];
__device__ int   g_rowptr[NN+1];
__device__ int   g_cursor[NN];
__device__ int   g_csrc[EA];       // CSR: src node per entry
__device__ int   g_ceid[EA];       // CSR: original edge id per entry

// ---------------------------------------------------------------------------
__global__ void init_deg_kernel(int* __restrict__ deg){
  int i = blockIdx.x*blockDim.x + threadIdx.x;
  if (i < NN) deg[i] = 1;          // self loop
}

__global__ void hist_kernel(const int* __restrict__ dst, int* __restrict__ deg){
  int e = blockIdx.x*blockDim.x + threadIdx.x;
  if (e < EE) atomicAdd(&deg[dst[e]], 1);
}

// single-block exclusive scan of deg -> rowptr (and cursor copy)
__global__ void scan_kernel(const int* __restrict__ deg, int* __restrict__ rowptr,
                            int* __restrict__ cursor){
  __shared__ int part[1024];
  int t = threadIdx.x;
  const int CH = (NN + 1023)/1024;
  int b = t*CH;
  int hi = min(b+CH, NN);
  int s = 0;
  for (int i = b; i < hi; i++) s += deg[i];
  part[t] = s;
  __syncthreads();
  for (int off = 1; off < 1024; off <<= 1){
    int add = (t >= off) ? part[t-off] : 0;
    __syncthreads();
    part[t] += add;
    __syncthreads();
  }
  int pre = (t == 0) ? 0 : part[t-1];
  for (int i = b; i < hi; i++){
    rowptr[i] = pre; cursor[i] = pre;
    pre += deg[i];
  }
  if (t == 1023) rowptr[NN] = part[1023];
}

__global__ void scatter_kernel(const int* __restrict__ src, const int* __restrict__ dst,
                               int* __restrict__ cursor,
                               int* __restrict__ csrc, int* __restrict__ ceid){
  int e = blockIdx.x*blockDim.x + threadIdx.x;
  if (e >= EA) return;
  int sN, dN;
  if (e < EE){ sN = src[e]; dN = dst[e]; } else { sN = dN = e - EE; }
  int pos = atomicAdd(&cursor[dN], 1);
  csrc[pos] = sN;
  ceid[pos] = e;
}

// loop_attr[n,:] = mean over real in-edges of edge_attr (warp per node, lane=dim)
__global__ void loop_gather_kernel(const int* __restrict__ rowptr, const int* __restrict__ ceid,
                                   const float* __restrict__ ea, float* __restrict__ lp){
  int warp = (blockIdx.x*blockDim.x + threadIdx.x) >> 5;
  int lane = threadIdx.x & 31;
  if (warp >= NN) return;
  int row = rowptr[warp], end = rowptr[warp+1];
  float s = 0.f; int cnt = 0;
  for (int i = row; i < end; i++){
    int eid = ceid[i];
    if (eid < EE){ s += ea[(size_t)eid*ED + lane]; cnt++; }
  }
  lp[(size_t)warp*ED + lane] = (cnt > 0) ? s/(float)cnt : 0.f;
}

// per-node attention scalars  a_i = <h[n,h,:],att_i[h]>,  a_j likewise
__global__ void aij_kernel(const float* __restrict__ h, const float* __restrict__ att,
                           float* __restrict__ ai, float* __restrict__ aj,
                           int H, int C){
  int idx = blockIdx.x*blockDim.x + threadIdx.x;
  if (idx >= NN*H) return;
  int n = idx / H, hh = idx - n*H;
  int stride = 2*C + ED;
  const float4* atti = reinterpret_cast<const float4*>(att + hh*stride);
  const float4* attj = reinterpret_cast<const float4*>(att + hh*stride + C);
  const float4* hv   = reinterpret_cast<const float4*>(h + ((size_t)n*H + hh)*C);
  float si = 0.f, sj = 0.f;
  for (int c = 0; c < C/4; c++){
    float4 v = hv[c], a = atti[c], b = attj[c];
    si += v.x*a.x + v.y*a.y + v.z*a.z + v.w*a.w;
    sj += v.x*b.x + v.y*b.y + v.z*b.z + v.w*b.w;
  }
  ai[idx] = si; aj[idx] = sj;
}

// per augmented edge: edge MLP -> gate -> att_e dot, add a_i+a_j, leaky_relu
template<int H>
__global__ void edge_alpha_kernel(const int* __restrict__ src, const int* __restrict__ dst,
    const float* __restrict__ ea, const float* __restrict__ loopattr,
    const float* __restrict__ ew1, const float* __restrict__ eb1,
    const float* __restrict__ ew2, const float* __restrict__ eb2,
    const float* __restrict__ att, int C,
    const float* __restrict__ ai, const float* __restrict__ aj,
    float* __restrict__ alpha){
  __shared__ float s_ew1[512], s_ew2[512], s_eb1[16], s_eb2[32], s_att[H*32];
  int t = threadIdx.x;
  for (int i = t; i < 512; i += 256){ s_ew1[i] = ew1[i]; s_ew2[i] = ew2[i]; }
  if (t < 16) s_eb1[t] = eb1[t];
  else if (t < 48) s_eb2[t-16] = eb2[t-16];
  for (int i = t; i < H*32; i += 256){
    int hh = i >> 5, d = i & 31;
    s_att[i] = att[hh*(2*C+ED) + 2*C + d];
  }
  __syncthreads();

  int e = blockIdx.x*blockDim.x + t;
  if (e >= EA) return;
  int sN, dN; const float* eav;
  if (e < EE){ sN = src[e]; dN = dst[e]; eav = ea + (size_t)e*ED; }
  else       { sN = dN = e - EE;         eav = loopattr + (size_t)(e-EE)*ED; }

  float eaL[32];
  #pragma unroll
  for (int d = 0; d < 32; d += 4){
    float4 v = *reinterpret_cast<const float4*>(eav + d);
    eaL[d] = v.x; eaL[d+1] = v.y; eaL[d+2] = v.z; eaL[d+3] = v.w;
  }
  float hid[16];
  #pragma unroll
  for (int j = 0; j < 16; j++) hid[j] = s_eb1[j];
  #pragma unroll
  for (int d = 0; d < 32; d++){
    float a = eaL[d];
    #pragma unroll
    for (int j = 0; j < 16; j++) hid[j] += a * s_ew1[d*16 + j];
  }
  #pragma unroll
  for (int j = 0; j < 16; j++) hid[j] = fmaxf(hid[j], 0.f);

  float acc[H];
  #pragma unroll
  for (int h = 0; h < H; h++) acc[h] = 0.f;
  #pragma unroll
  for (int d = 0; d < 32; d++){
    float o = s_eb2[d];
    #pragma unroll
    for (int j = 0; j < 16; j++) o += hid[j] * s_ew2[j*32 + d];
    float cw = 1.f / (1.f + expf(-o));
    float ew = eaL[d] * cw;
    #pragma unroll
    for (int h = 0; h < H; h++) acc[h] += ew * s_att[h*32 + d];
  }
  #pragma unroll
  for (int h = 0; h < H; h++){
    float tt  = ai[dN*H + h] + aj[sN*H + h] + acc[h];
    alpha[(size_t)e*H + h] = tt > 0.f ? tt : 0.2f*tt;
  }
}

// fused per-dst-node: softmax over in-edges + weighted gather-sum + bias(+BN+ELU)
// one warp per node; lane covers float4 feature chunks.
template<int H, int C, bool FINAL>
__global__ void agg_fused_kernel(const int* __restrict__ rowptr,
    const int* __restrict__ csrc, const int* __restrict__ ceid,
    const float* __restrict__ hfeat, const float* __restrict__ alpha,
    const float* __restrict__ bias, const float* __restrict__ gamma,
    const float* __restrict__ beta, const float* __restrict__ mean,
    const float* __restrict__ var, float* __restrict__ outp){
  const int HC  = H*C;
  const int NCH = HC/4;                 // float4 chunks
  const int CPL = (NCH + 31)/32;        // chunks per lane (2 for 256, else 1)
  int warp = (blockIdx.x*blockDim.x + threadIdx.x) >> 5;
  int lane = threadIdx.x & 31;
  if (warp >= NN) return;
  int row = rowptr[warp], end = rowptr[warp+1];

  // pass 1: per-head max over this node's edges
  float mx[H];
  #pragma unroll
  for (int h = 0; h < H; h++) mx[h] = -1e30f;
  for (int i = row + lane; i < end; i += 32){
    int eid = ceid[i];
    #pragma unroll
    for (int h = 0; h < H; h++)
      mx[h] = fmaxf(mx[h], alpha[(size_t)eid*H + h]);
  }
  #pragma unroll
  for (int h = 0; h < H; h++)
    #pragma unroll
    for (int o = 16; o > 0; o >>= 1)
      mx[h] = fmaxf(mx[h], __shfl_xor_sync(0xffffffffu, mx[h], o));

  // pass 2: per-head softmax denominator
  float sm[H];
  #pragma unroll
  for (int h = 0; h < H; h++) sm[h] = 0.f;
  for (int i = row + lane; i < end; i += 32){
    int eid = ceid[i];
    #pragma unroll
    for (int h = 0; h < H; h++)
      sm[h] += expf(alpha[(size_t)eid*H + h] - mx[h]);
  }
  #pragma unroll
  for (int h = 0; h < H; h++)
    #pragma unroll
    for (int o = 16; o > 0; o >>= 1)
      sm[h] += __shfl_xor_sync(0xffffffffu, sm[h], o);

  // pass 3: exp-weighted gather accumulation (serial over edges, lanes over features)
  float4 acc[CPL];
  #pragma unroll
  for (int c = 0; c < CPL; c++) acc[c] = make_float4(0.f,0.f,0.f,0.f);
  for (int i = row; i < end; i++){
    int src = csrc[i];
    int eid = ceid[i];
    const float4* hp = reinterpret_cast<const float4*>(hfeat + (size_t)src*HC);
    #pragma unroll
    for (int c = 0; c < CPL; c++){
      int j = lane + 32*c;
      if (j < NCH){
        int head = (j*4)/C;
        float w = expf(alpha[(size_t)eid*H + head] - mx[head]);
        float4 v = hp[j];
        acc[c].x += w*v.x; acc[c].y += w*v.y; acc[c].z += w*v.z; acc[c].w += w*v.w;
      }
    }
  }

  // epilogue: normalize + bias (+BN+ELU) and store
  #pragma unroll
  for (int c = 0; c < CPL; c++){
    int j = lane + 32*c;
    if (j < NCH){
      int head = (j*4)/C;
      float inv = 1.f/(sm[head] + 1e-16f);
      float vv[4] = {acc[c].x*inv, acc[c].y*inv, acc[c].z*inv, acc[c].w*inv};
      float4 o;
      float* op = &o.x;
      #pragma unroll
      for (int k = 0; k < 4; k++){
        int col = j*4 + k;
        float v = vv[k] + bias[col];
        if (!FINAL){
          v = (v - mean[col]) * rsqrtf(var[col] + 1e-5f) * gamma[col] + beta[col];
          v = v > 0.f ? v : expf(v) - 1.f;
        }
        op[k] = v;
      }
      *reinterpret_cast<float4*>(outp + (size_t)warp*HC + j*4) = o;
    }
  }
}

// C[M,N] = A[M,K] @ B[K,N], fp32. 128x64 tile, BK=16, 8x4 microtile, 256 thr.
__global__ void gemm_kernel(const float* __restrict__ A, const float* __restrict__ B,
                            float* __restrict__ C, int M, int K, int N){
  __shared__ float As[16][136];
  __shared__ float Bs[16][64];
  int tid = threadIdx.x;
  int tx = tid & 15;
  int ty = tid >> 4;
  int rowBase = blockIdx.y*128, colBase = blockIdx.x*64;

  float acc[8][4];
  #pragma unroll
  for (int i = 0; i < 8; i++)
    #pragma unroll
    for (int j = 0; j < 4; j++) acc[i][j] = 0.f;

  for (int k0 = 0; k0 < K; k0 += 16){
    #pragma unroll
    for (int i = 0; i < 2; i++){
      int lin = tid + i*256;
      int row = lin >> 2;
      int kq  = lin & 3;
      int gr  = rowBase + row;
      float4 v = make_float4(0.f,0.f,0.f,0.f);
      if (gr < M) v = *reinterpret_cast<const float4*>(A + (size_t)gr*K + k0 + kq*4);
      As[kq*4+0][row] = v.x; As[kq*4+1][row] = v.y;
      As[kq*4+2][row] = v.z; As[kq*4+3][row] = v.w;
    }
    {
      int kk = tid >> 4;
      int nq = tid & 15;
      *reinterpret_cast<float4*>(&Bs[kk][nq*4]) =
        *reinterpret_cast<const float4*>(B + (size_t)(k0+kk)*N + colBase + nq*4);
    }
    __syncthreads();
    #pragma unroll
    for (int kk = 0; kk < 16; kk++){
      float4 a0 = *reinterpret_cast<const float4*>(&As[kk][ty*8]);
      float4 a1 = *reinterpret_cast<const float4*>(&As[kk][ty*8+4]);
      float4 b  = *reinterpret_cast<const float4*>(&Bs[kk][tx*4]);
      float av[8] = {a0.x,a0.y,a0.z,a0.w,a1.x,a1.y,a1.z,a1.w};
      float bv[4] = {b.x,b.y,b.z,b.w};
      #pragma unroll
      for (int i = 0; i < 8; i++)
        #pragma unroll
        for (int j = 0; j < 4; j++) acc[i][j] += av[i]*bv[j];
    }
    __syncthreads();
  }
  #pragma unroll
  for (int i = 0; i < 8; i++){
    int row = rowBase + ty*8 + i;
    if (row < M){
      float4 v = make_float4(acc[i][0],acc[i][1],acc[i][2],acc[i][3]);
      *reinterpret_cast<float4*>(C + (size_t)row*N + colBase + tx*4) = v;
    }
  }
}

// ---------------------------------------------------------------------------
static inline int cdiv(int a, int b){ return (a + b - 1)/b; }

extern "C" void kernel_launch(void* const* d_in, const int* in_sizes, int n_in,
                              void* d_out, int out_size){
  const float* x   = (const float*)d_in[0];
  const int*   ei  = (const int*)  d_in[1];
  const float* ea  = (const float*)d_in[2];
  const float *g1W   =(const float*)d_in[3],  *g1e1=(const float*)d_in[4],  *g1b1=(const float*)d_in[5],
              *g1e2  =(const float*)d_in[6],  *g1b2=(const float*)d_in[7],  *g1att=(const float*)d_in[8],
              *g1bias=(const float*)d_in[9];
  const float *g2W   =(const float*)d_in[10], *g2e1=(const float*)d_in[11], *g2b1=(const float*)d_in[12],
              *g2e2  =(const float*)d_in[13], *g2b2=(const float*)d_in[14], *g2att=(const float*)d_in[15],
              *g2bias=(const float*)d_in[16];
  const float *g3W   =(const float*)d_in[17], *g3e1=(const float*)d_in[18], *g3b1=(const float*)d_in[19],
              *g3e2  =(const float*)d_in[20], *g3b2=(const float*)d_in[21], *g3att=(const float*)d_in[22],
              *g3bias=(const float*)d_in[23];
  const float *bn1g=(const float*)d_in[24], *bn1b=(const float*)d_in[25],
              *bn1m=(const float*)d_in[26], *bn1v=(const float*)d_in[27];
  const float *bn2g=(const float*)d_in[28], *bn2b=(const float*)d_in[29],
              *bn2m=(const float*)d_in[30], *bn2v=(const float*)d_in[31];
  const int* srcp = ei;
  const int* dstp = ei + EE;
  float* outp = (float*)d_out;

  float *ph, *pfA, *pfB, *pai, *paj, *palpha, *ploop;
  int *pdeg, *prow, *pcur, *pcsrc, *pceid;
  cudaGetSymbolAddress((void**)&ph,     g_h);
  cudaGetSymbolAddress((void**)&pfA,    g_featA);
  cudaGetSymbolAddress((void**)&pfB,    g_featB);
  cudaGetSymbolAddress((void**)&pai,    g_ai);
  cudaGetSymbolAddress((void**)&paj,    g_aj);
  cudaGetSymbolAddress((void**)&palpha, g_alpha);
  cudaGetSymbolAddress((void**)&ploop,  g_loop);
  cudaGetSymbolAddress((void**)&pdeg,   g_deg);
  cudaGetSymbolAddress((void**)&prow,   g_rowptr);
  cudaGetSymbolAddress((void**)&pcur,   g_cursor);
  cudaGetSymbolAddress((void**)&pcsrc,  g_csrc);
  cudaGetSymbolAddress((void**)&pceid,  g_ceid);

  const int TB = 256;
  const int WARP_GRID = cdiv(NN, TB/32);   // one warp per node

  // -------- CSR build (layer invariant) --------
  init_deg_kernel<<<cdiv(NN,TB),TB>>>(pdeg);
  hist_kernel<<<cdiv(EE,TB),TB>>>(dstp, pdeg);
  scan_kernel<<<1,1024>>>(pdeg, prow, pcur);
  scatter_kernel<<<cdiv(EA,TB),TB>>>(srcp, dstp, pcur, pcsrc, pceid);
  loop_gather_kernel<<<WARP_GRID,TB>>>(prow, pceid, ea, ploop);

  // -------- layer 1: 128 -> 4x64 (concat 256), BN1 + ELU --------
  {
    const int K=128, H=4, C=64, HC=256;
    dim3 g(HC/64, cdiv(NN,128));
    gemm_kernel<<<g,256>>>(x, g1W, ph, NN, K, HC);
    aij_kernel<<<cdiv(NN*H,TB),TB>>>(ph, g1att, pai, paj, H, C);
    edge_alpha_kernel<4><<<cdiv(EA,TB),TB>>>(srcp,dstp,ea,ploop,g1e1,g1b1,g1e2,g1b2,g1att,C,pai,paj,palpha);
    agg_fused_kernel<4,64,false><<<WARP_GRID,TB>>>(prow,pcsrc,pceid,ph,palpha,
        g1bias,bn1g,bn1b,bn1m,bn1v,pfA);
  }

  // -------- layer 2: 256 -> 4x32 (concat 128), BN2 + ELU --------
  {
    const int K=256, H=4, C=32, HC=128;
    dim3 g(HC/64, cdiv(NN,128));
    gemm_kernel<<<g,256>>>(pfA, g2W, ph, NN, K, HC);
    aij_kernel<<<cdiv(NN*H,TB),TB>>>(ph, g2att, pai, paj, H, C);
    edge_alpha_kernel<4><<<cdiv(EA,TB),TB>>>(srcp,dstp,ea,ploop,g2e1,g2b1,g2e2,g2b2,g2att,C,pai,paj,palpha);
    agg_fused_kernel<4,32,false><<<WARP_GRID,TB>>>(prow,pcsrc,pceid,ph,palpha,
        g2bias,bn2g,bn2b,bn2m,bn2v,pfB);
  }

  // -------- layer 3: 128 -> 1x64 (mean over 1 head = identity) --------
  {
    const int K=128, H=1, C=64, HC=64;
    dim3 g(HC/64, cdiv(NN,128));
    gemm_kernel<<<g,256>>>(pfB, g3W, ph, NN, K, HC);
    aij_kernel<<<cdiv(NN*H,TB),TB>>>(ph, g3att, pai, paj, H, C);
    edge_alpha_kernel<1><<<cdiv(EA,TB),TB>>>(srcp,dstp,ea,ploop,g3e1,g3b1,g3e2,g3b2,g3att,C,pai,paj,palpha);
    agg_fused_kernel<1,64,true><<<WARP_GRID,TB>>>(prow,pcsrc,pceid,ph,palpha,
        g3bias,nullptr,nullptr,nullptr,nullptr,outp);
  }
}